// round 16
// baseline (speedup 1.0000x reference)
#include <cuda_runtime.h>
#include <cuda_bf16.h>

// Fixed shapes from setup_inputs: B=128, N=10000, din=64, draw=64, T=8, D=128
#define B_MAX   128
#define N_MAX   10000
#define DIN     64
#define DMODL   128
#define RPW     40           // rows per WARP chunk (40%4==0 -> norm no straddle)
#define WPB     8            // warps per block
#define RPBLK   (RPW * WPB)  // 320 rows per block
#define NCHUNK  250          // 10000 / 40
#define MAXCH   256          // >= NCHUNK

// Static scratch (no allocations allowed)
__device__ float g_E[(size_t)B_MAX * N_MAX];     // MASKED exp(e - m_chunk)
__device__ float g_pm[B_MAX * MAXCH];            // per-chunk masked max
__device__ float g_ps[B_MAX * MAXCH];            // per-chunk masked sum of exp
__device__ float g_scale[B_MAX * MAXCH];         // exp(m_chunk - m)/S

// ---------------------------------------------------------------------------
// main: WARP-LOCAL softmax chunks. Each warp owns 40 contiguous rows:
//   - streams raw_x (__ldcs), 4 rows per iteration, e kept in registers
//   - warp-shuffle max / sum, NO __syncthreads, NO smem
//   - lane8==0 lanes store masked exp(e - m_warp) to g_E (16B/iter, coalesced)
// ---------------------------------------------------------------------------
__global__ __launch_bounds__(256)
void main_kernel(const float* __restrict__ raw_x,
                 const float* __restrict__ x,
                 const float* __restrict__ a,
                 const float* __restrict__ adj_mask,
                 const int*   __restrict__ node_index,
                 const int*   __restrict__ type_index,
                 int N) {
    const int b     = blockIdx.y;
    const int tid   = threadIdx.x;
    const int warp  = tid >> 5;
    const int lane  = tid & 31;
    const int lane8 = lane & 7;
    const int grp   = lane >> 3;                  // 0..3 : row within iteration
    const int wbase = blockIdx.x * RPBLK + warp * RPW;
    const int chunkIdx = blockIdx.x * WPB + warp; // 0..255; valid < NCHUNK
    const bool owner = (lane8 == 0);

    const int t  = type_index[b];
    const int ni = node_index[0];

    // ---- per-warp c = dot(x[b,ni,:], a[t,0:64]) ----
    const float* xp = x + ((size_t)b * N + ni) * DIN;
    const float* aw = a + t * DMODL;
    float cv = xp[lane] * aw[lane] + xp[lane + 32] * aw[lane + 32];
    cv += __shfl_xor_sync(0xffffffffu, cv, 16);
    cv += __shfl_xor_sync(0xffffffffu, cv, 8);
    cv += __shfl_xor_sync(0xffffffffu, cv, 4);
    cv += __shfl_xor_sync(0xffffffffu, cv, 2);
    cv += __shfl_xor_sync(0xffffffffu, cv, 1);
    const float c = cv;

    // ---- weights for this thread's 8 columns ----
    const float* ap = aw + DIN;
    const float4 wa = *reinterpret_cast<const float4*>(ap + lane8 * 4);
    const float4 wb = *reinterpret_cast<const float4*>(ap + 32 + lane8 * 4);

    const float* base = raw_x + (size_t)b * N * DIN;

    // ---- stream 40 rows: 10 iterations x 4 rows; e kept in registers ----
    float ev[RPW / 4];
    unsigned mbits = 0;
    float lmax = -3.0e38f;
#pragma unroll
    for (int i = 0; i < RPW / 4; ++i) {
        const int n = wbase + i * 4 + grp;
        const bool valid = n < N;
        float p = 0.f;
        if (valid) {
            const float4* r = reinterpret_cast<const float4*>(
                                  base + (size_t)n * DIN);
            float4 va = __ldcs(r + lane8);       // evict-first: read-once stream
            float4 vb = __ldcs(r + 8 + lane8);
            p = va.x * wa.x + va.y * wa.y + va.z * wa.z + va.w * wa.w
              + vb.x * wb.x + vb.y * wb.y + vb.z * wb.z + vb.w * wb.w;
        }
        p += __shfl_xor_sync(0xffffffffu, p, 1);
        p += __shfl_xor_sync(0xffffffffu, p, 2);
        p += __shfl_xor_sync(0xffffffffu, p, 4);
        float e = c + p;
        e = (e > 0.f) ? e : 0.01f * e;            // leaky relu
        ev[i] = e;
        if (valid && owner) {
            if (adj_mask[n] > 0.f) {
                mbits |= (1u << i);
                lmax = fmaxf(lmax, e);
            }
        }
    }

    // ---- warp max (owners contributed; all lanes receive) ----
    lmax = fmaxf(lmax, __shfl_xor_sync(0xffffffffu, lmax, 1));
    lmax = fmaxf(lmax, __shfl_xor_sync(0xffffffffu, lmax, 2));
    lmax = fmaxf(lmax, __shfl_xor_sync(0xffffffffu, lmax, 4));
    lmax = fmaxf(lmax, __shfl_xor_sync(0xffffffffu, lmax, 8));
    lmax = fmaxf(lmax, __shfl_xor_sync(0xffffffffu, lmax, 16));

    // ---- exp pass: masked exp, store, accumulate sum ----
    float s = 0.f;
#pragma unroll
    for (int i = 0; i < RPW / 4; ++i) {
        const int n = wbase + i * 4 + grp;
        if (owner && n < N) {
            float ex = (mbits >> i & 1u) ? __expf(ev[i] - lmax) : 0.f;
            g_E[(size_t)b * N + n] = ex;
            s += ex;
        }
    }
    s += __shfl_xor_sync(0xffffffffu, s, 1);
    s += __shfl_xor_sync(0xffffffffu, s, 2);
    s += __shfl_xor_sync(0xffffffffu, s, 4);
    s += __shfl_xor_sync(0xffffffffu, s, 8);
    s += __shfl_xor_sync(0xffffffffu, s, 16);

    if (lane == 0 && chunkIdx < NCHUNK) {
        g_pm[b * MAXCH + chunkIdx] = lmax;
        g_ps[b * MAXCH + chunkIdx] = s;
    }
}

// ---------------------------------------------------------------------------
// combine: per b reduce 250 chunk partials -> per-chunk scales. 1 warp per b.
// ---------------------------------------------------------------------------
__global__ void combine_kernel(int chunks) {
    const int b = blockIdx.x;
    const int lane = threadIdx.x;
    const int K = MAXCH / 32;             // 8 slots per lane

    float pm[K], ps[K];
#pragma unroll
    for (int k = 0; k < K; ++k) {
        int idx = lane + k * 32;
        pm[k] = (idx < chunks) ? g_pm[b * MAXCH + idx] : -3.0e38f;
        ps[k] = (idx < chunks) ? g_ps[b * MAXCH + idx] : 0.f;
    }

    float m = pm[0];
#pragma unroll
    for (int k = 1; k < K; ++k) m = fmaxf(m, pm[k]);
    m = fmaxf(m, __shfl_xor_sync(0xffffffffu, m, 16));
    m = fmaxf(m, __shfl_xor_sync(0xffffffffu, m, 8));
    m = fmaxf(m, __shfl_xor_sync(0xffffffffu, m, 4));
    m = fmaxf(m, __shfl_xor_sync(0xffffffffu, m, 2));
    m = fmaxf(m, __shfl_xor_sync(0xffffffffu, m, 1));

    float f[K];
    float s = 0.f;
#pragma unroll
    for (int k = 0; k < K; ++k) {
        f[k] = __expf(pm[k] - m);         // 0 for absent chunks (pm=-3e38)
        s += ps[k] * f[k];
    }
    s += __shfl_xor_sync(0xffffffffu, s, 16);
    s += __shfl_xor_sync(0xffffffffu, s, 8);
    s += __shfl_xor_sync(0xffffffffu, s, 4);
    s += __shfl_xor_sync(0xffffffffu, s, 2);
    s += __shfl_xor_sync(0xffffffffu, s, 1);
    const float inv = 1.0f / s;

#pragma unroll
    for (int k = 0; k < K; ++k) {
        int idx = lane + k * 32;
        if (idx < chunks) g_scale[b * MAXCH + idx] = f[k] * inv;
    }
}

// ---------------------------------------------------------------------------
// norm: pure scaled copy (E already masked): out = E * scale[b, n/RPW].
// 2 float4 per thread.  RPW%4==0 -> no float4 straddles a chunk.
// ---------------------------------------------------------------------------
__global__ __launch_bounds__(256)
void norm_kernel(float* __restrict__ out, int N) {
    const int b  = blockIdx.y;
    const int n4 = N >> 2;                  // 2500
    const float4* E4 = reinterpret_cast<const float4*>(g_E + (size_t)b * N);
    float4* O4 = reinterpret_cast<float4*>(out + (size_t)b * N);

#pragma unroll
    for (int k = 0; k < 2; ++k) {
        int idx = blockIdx.x * 512 + k * 256 + threadIdx.x;
        if (idx < n4) {
            float4 e = E4[idx];
            float sc = g_scale[b * MAXCH + (idx * 4) / RPW];
            float4 o;
            o.x = e.x * sc;
            o.y = e.y * sc;
            o.z = e.z * sc;
            o.w = e.w * sc;
            O4[idx] = o;
        }
    }
}

// ---------------------------------------------------------------------------
extern "C" void kernel_launch(void* const* d_in, const int* in_sizes, int n_in,
                              void* d_out, int out_size) {
    const float* x          = (const float*)d_in[0];
    const float* raw_x      = (const float*)d_in[1];
    const float* a          = (const float*)d_in[2];
    const float* adj_mask   = (const float*)d_in[3];
    const int*   node_index = (const int*)  d_in[4];
    const int*   type_index = (const int*)  d_in[5];
    float* out = (float*)d_out;

    const int N = in_sizes[3];                       // adj_mask: (N,)
    const int B = in_sizes[5];                       // type_index: (B,)
    const int blocksX = (N + RPBLK - 1) / RPBLK;     // 32
    const int chunks  = (N + RPW - 1) / RPW;         // 250

    main_kernel<<<dim3(blocksX, B), 256>>>(raw_x, x, a, adj_mask,
                                           node_index, type_index, N);
    combine_kernel<<<B, 32>>>(chunks);

    const int n4 = N >> 2;
    norm_kernel<<<dim3((n4 + 511) / 512, B), 256>>>(out, N);
}

// round 17
// speedup vs baseline: 1.1754x; 1.1754x over previous
#include <cuda_runtime.h>
#include <cuda_bf16.h>

// Fixed shapes from setup_inputs: B=128, N=10000, din=64, draw=64, T=8, D=128
#define B_MAX   128
#define N_MAX   10000
#define DIN     64
#define DMODL   128
#define RPB     200          // rows (n) per main tile (50*200=10000)
#define MAXCH   64           // >= chunks = N/RPB = 50

// Static scratch (no allocations allowed)
__device__ float g_E[(size_t)B_MAX * N_MAX];     // exp(e - m_chunk)
__device__ float g_pm[B_MAX * MAXCH];            // per-chunk masked max
__device__ float g_ps[B_MAX * MAXCH];            // per-chunk masked sum of exp
__device__ float g_scale[B_MAX * MAXCH];         // exp(m_chunk - m)/S

// ---------------------------------------------------------------------------
// main: one block per (b, chunk of 200 rows). Streams raw_x once (__ldcs).
//   Measured optimum (R10): per-warp c (no barrier before the stream),
//   leaky-relu applied in-loop, block-level chunk softmax in phase 2.
// ---------------------------------------------------------------------------
__global__ __launch_bounds__(256)
void main_kernel(const float* __restrict__ raw_x,
                 const float* __restrict__ x,
                 const float* __restrict__ a,
                 const float* __restrict__ adj_mask,
                 const int*   __restrict__ node_index,
                 const int*   __restrict__ type_index,
                 int N) {
    const int b     = blockIdx.y;
    const int chunk = blockIdx.x;
    const int tid   = threadIdx.x;
    const int warp  = tid >> 5;
    const int lane  = tid & 31;
    const int lane8 = lane & 7;
    const int grp   = lane >> 3;          // 0..3 : row within warp-iteration
    const int n0    = chunk * RPB;

    __shared__ float e_sm[RPB];
    __shared__ float red[64];
    __shared__ float bcast;

    const int t  = type_index[b];
    const int ni = node_index[0];

    // ---- per-warp c (no barrier; independent of the raw_x stream) ----
    const float* xp = x + ((size_t)b * N + ni) * DIN;
    const float* aw = a + t * DMODL;
    float cv = xp[lane] * aw[lane] + xp[lane + 32] * aw[lane + 32];
    cv += __shfl_xor_sync(0xffffffffu, cv, 16);
    cv += __shfl_xor_sync(0xffffffffu, cv, 8);
    cv += __shfl_xor_sync(0xffffffffu, cv, 4);
    cv += __shfl_xor_sync(0xffffffffu, cv, 2);
    cv += __shfl_xor_sync(0xffffffffu, cv, 1);
    const float c = cv;

    // ---- weights for this thread's 8 columns ----
    const float* ap = aw + DIN;
    const float4 wa = *reinterpret_cast<const float4*>(ap + lane8 * 4);
    const float4 wb = *reinterpret_cast<const float4*>(ap + 32 + lane8 * 4);

    const float* base = raw_x + (size_t)b * N * DIN;

    // ---- phase 1: 32 rows per block-iteration (4 per warp) ----
    const int ITERS = (RPB + 31) >> 5;    // 7 (6 full + 8-row tail)
#pragma unroll
    for (int i = 0; i < ITERS; ++i) {
        int nl = i * 32 + warp * 4 + grp;
        bool valid = nl < RPB;
        float p = 0.f;
        if (valid) {
            const float4* r = reinterpret_cast<const float4*>(
                                  base + (size_t)(n0 + nl) * DIN);
            float4 va = __ldcs(r + lane8);       // evict-first: read-once stream
            float4 vb = __ldcs(r + 8 + lane8);
            p = va.x * wa.x + va.y * wa.y + va.z * wa.z + va.w * wa.w
              + vb.x * wb.x + vb.y * wb.y + vb.z * wb.z + vb.w * wb.w;
        }
        p += __shfl_xor_sync(0xffffffffu, p, 1);
        p += __shfl_xor_sync(0xffffffffu, p, 2);
        p += __shfl_xor_sync(0xffffffffu, p, 4);
        if (valid && lane8 == 0) {
            float e = c + p;
            e_sm[nl] = (e > 0.f) ? e : 0.01f * e;   // leaky relu
        }
    }
    __syncthreads();

    // ---- phase 2a: masked max over chunk (tid < RPB handles one row) ----
    const bool has0 = tid < RPB;
    float m0 = 0.f, e0 = 0.f;
    if (has0) { m0 = adj_mask[n0 + tid]; e0 = e_sm[tid]; }

    float lmax = (has0 && m0 > 0.f) ? e0 : -3.0e38f;
    lmax = fmaxf(lmax, __shfl_xor_sync(0xffffffffu, lmax, 16));
    lmax = fmaxf(lmax, __shfl_xor_sync(0xffffffffu, lmax, 8));
    lmax = fmaxf(lmax, __shfl_xor_sync(0xffffffffu, lmax, 4));
    lmax = fmaxf(lmax, __shfl_xor_sync(0xffffffffu, lmax, 2));
    lmax = fmaxf(lmax, __shfl_xor_sync(0xffffffffu, lmax, 1));
    if (lane == 0) red[warp] = lmax;
    __syncthreads();
    if (tid == 0) {
        float v = red[0];
#pragma unroll
        for (int i = 1; i < 8; ++i) v = fmaxf(v, red[i]);
        bcast = v;
    }
    __syncthreads();
    const float m_blk = bcast;

    // ---- phase 2b: exp, store, masked sum ----
    float s = 0.f;
    if (has0) {
        float ex0 = __expf(e0 - m_blk);
        g_E[(size_t)b * N + n0 + tid] = ex0;
        if (m0 > 0.f) s += ex0;
    }
    s += __shfl_xor_sync(0xffffffffu, s, 16);
    s += __shfl_xor_sync(0xffffffffu, s, 8);
    s += __shfl_xor_sync(0xffffffffu, s, 4);
    s += __shfl_xor_sync(0xffffffffu, s, 2);
    s += __shfl_xor_sync(0xffffffffu, s, 1);
    if (lane == 0) red[32 + warp] = s;
    __syncthreads();
    if (tid == 0) {
        float tot = red[32];
#pragma unroll
        for (int i = 1; i < 8; ++i) tot += red[32 + i];
        g_pm[b * MAXCH + chunk] = m_blk;
        g_ps[b * MAXCH + chunk] = tot;
    }
}

// ---------------------------------------------------------------------------
// combine: per b reduce chunk partials -> per-chunk normalization scales.
// ---------------------------------------------------------------------------
__global__ void combine_kernel(int chunks) {
    const int b = blockIdx.x;
    const int lane = threadIdx.x;
    float pm0 = (lane < chunks)      ? g_pm[b * MAXCH + lane]      : -3.0e38f;
    float pm1 = (lane + 32 < chunks) ? g_pm[b * MAXCH + lane + 32] : -3.0e38f;
    float ps0 = (lane < chunks)      ? g_ps[b * MAXCH + lane]      : 0.f;
    float ps1 = (lane + 32 < chunks) ? g_ps[b * MAXCH + lane + 32] : 0.f;

    float m = fmaxf(pm0, pm1);
    m = fmaxf(m, __shfl_xor_sync(0xffffffffu, m, 16));
    m = fmaxf(m, __shfl_xor_sync(0xffffffffu, m, 8));
    m = fmaxf(m, __shfl_xor_sync(0xffffffffu, m, 4));
    m = fmaxf(m, __shfl_xor_sync(0xffffffffu, m, 2));
    m = fmaxf(m, __shfl_xor_sync(0xffffffffu, m, 1));

    float f0 = __expf(pm0 - m);
    float f1 = __expf(pm1 - m);
    float s = ps0 * f0 + ps1 * f1;
    s += __shfl_xor_sync(0xffffffffu, s, 16);
    s += __shfl_xor_sync(0xffffffffu, s, 8);
    s += __shfl_xor_sync(0xffffffffu, s, 4);
    s += __shfl_xor_sync(0xffffffffu, s, 2);
    s += __shfl_xor_sync(0xffffffffu, s, 1);
    float inv = 1.0f / s;

    if (lane < chunks)      g_scale[b * MAXCH + lane]      = f0 * inv;
    if (lane + 32 < chunks) g_scale[b * MAXCH + lane + 32] = f1 * inv;
}

// ---------------------------------------------------------------------------
// norm: flat, no prologue. out = mask>0 ? g_E * scale[b,chunk] : 0.
// One float4 per thread, grid (ceil(n4/256), B).  RPB%4==0 -> no straddle.
// ---------------------------------------------------------------------------
__global__ __launch_bounds__(256)
void norm_kernel(const float* __restrict__ adj_mask,
                 float* __restrict__ out, int N) {
    const int b   = blockIdx.y;
    const int idx = blockIdx.x * 256 + threadIdx.x;
    const int n4  = N >> 2;                 // 2500
    if (idx >= n4) return;

    float4 e  = *reinterpret_cast<const float4*>(g_E + (size_t)b * N + idx * 4);
    float4 mm = reinterpret_cast<const float4*>(adj_mask)[idx];
    float sc  = g_scale[b * MAXCH + (idx * 4) / RPB];
    float4 o;
    o.x = (mm.x > 0.f) ? e.x * sc : 0.f;
    o.y = (mm.y > 0.f) ? e.y * sc : 0.f;
    o.z = (mm.z > 0.f) ? e.z * sc : 0.f;
    o.w = (mm.w > 0.f) ? e.w * sc : 0.f;
    *reinterpret_cast<float4*>(out + (size_t)b * N + idx * 4) = o;
}

// ---------------------------------------------------------------------------
extern "C" void kernel_launch(void* const* d_in, const int* in_sizes, int n_in,
                              void* d_out, int out_size) {
    const float* x          = (const float*)d_in[0];
    const float* raw_x      = (const float*)d_in[1];
    const float* a          = (const float*)d_in[2];
    const float* adj_mask   = (const float*)d_in[3];
    const int*   node_index = (const int*)  d_in[4];
    const int*   type_index = (const int*)  d_in[5];
    float* out = (float*)d_out;

    const int N = in_sizes[3];                 // adj_mask: (N,)
    const int B = in_sizes[5];                 // type_index: (B,)
    const int chunks = (N + RPB - 1) / RPB;    // 50

    main_kernel<<<dim3(chunks, B), 256>>>(raw_x, x, a, adj_mask,
                                          node_index, type_index, N);
    combine_kernel<<<B, 32>>>(chunks);

    const int n4 = N >> 2;
    norm_kernel<<<dim3((n4 + 255) / 256, B), 256>>>(adj_mask, out, N);
}